// round 15
// baseline (speedup 1.0000x reference)
#include <cuda_runtime.h>
#include <cuda_fp16.h>
#include <math.h>
#include <stdint.h>

#define HH 128
#define WW 128
#define CIN 1024
#define CMID 512
#define NA 6
#define HW (HH*WW)
#define NANCH (HW*NA)
#define PRE_N 6000
#define POST_N 300
#define KTOT 9216
#define TPAD 130
#define TROWS (TPAD*TPAD)   // 16900
#define NTILES 2048         // 128 rows x 16 co-tiles(32)
#define NSTAGES 96          // 3 ky x 32 chunks of 32 channels

// smem per buffer: A 2 splits x (130 rows x 80B) = 20800, B 3 kx x 2 splits x (32 x 80B) = 15360
#define ABUF_SZ 20800
#define STAGE_SZ 36160
#define NBUF 3
#define SMEM_SZ  (NBUF*STAGE_SZ)   // 108480

// ---------------- device scratch ----------------
__device__ __align__(16) __half g_X[2u*TROWS*CIN];       // padded input splits [s][row][c]
__device__ __align__(16) __half g_Ws[2u*9*CMID*CIN];     // weight splits [s][tap][co][c]
__device__ __align__(16) float g_conv1[CMID*HW];
__device__ unsigned int g_tile;
__device__ float g_boxes[NANCH*4];
__device__ float g_scores[NANCH];
__device__ unsigned int g_hist[4096];
__device__ unsigned int g_state[8];
__device__ unsigned int g_cnt[2];
__device__ int g_great[PRE_N + 256];
__device__ int g_tie[2048];
__device__ int g_sel[PRE_N];
__device__ float g_selbox[PRE_N*4];
__device__ float g_selscore[PRE_N];

__constant__ float c_dims[NA] = {16.f, 32.f, 64.f, 128.f, 256.f, 512.f};

// ---------------- helpers ----------------
__device__ __forceinline__ uint32_t smem_u32(const void* p) {
    uint32_t a;
    asm("{ .reg .u64 t; cvta.to.shared.u64 t, %1; cvt.u32.u64 %0, t; }" : "=r"(a) : "l"(p));
    return a;
}
__device__ __forceinline__ void cp16(uint32_t dst, const void* src) {
    asm volatile("cp.async.cg.shared.global [%0], [%1], 16;" :: "r"(dst), "l"(src) : "memory");
}
__device__ __forceinline__ void ldsm4(uint32_t* r, uint32_t addr) {
    asm volatile("ldmatrix.sync.aligned.m8n8.x4.shared.b16 {%0,%1,%2,%3}, [%4];"
        : "=r"(r[0]), "=r"(r[1]), "=r"(r[2]), "=r"(r[3]) : "r"(addr));
}
__device__ __forceinline__ void mma16816(float* d, const uint32_t* a, const uint32_t* b) {
    asm volatile("mma.sync.aligned.m16n8k16.row.col.f32.f16.f16.f32 "
        "{%0,%1,%2,%3}, {%4,%5,%6,%7}, {%8,%9}, {%0,%1,%2,%3};"
        : "+f"(d[0]), "+f"(d[1]), "+f"(d[2]), "+f"(d[3])
        : "r"(a[0]), "r"(a[1]), "r"(a[2]), "r"(a[3]), "r"(b[0]), "r"(b[1]));
}
// fp16 scaled 2-way split: v = h + m/2048
__device__ __forceinline__ void split2(float v, __half& h, __half& m) {
    h = __float2half(v);
    float r = v - __half2float(h);
    m = __float2half(r * 2048.f);
}
__device__ __forceinline__ uint32_t pk(__half a, __half b) {
    unsigned short x = *(unsigned short*)&a, y = *(unsigned short*)&b;
    return (uint32_t)x | ((uint32_t)y << 16);
}

// ---------------- weight split ----------------
__global__ void wsplit_kernel(const float* __restrict__ Wc) {
    int idx = blockIdx.x*blockDim.x + threadIdx.x;
    if (idx >= CMID*CIN) return;
    int co = idx >> 10, c = idx & 1023;
#pragma unroll
    for (int p = 0; p < 9; p++) {
        float v = Wc[(size_t)co*KTOT + c*9 + p];
        __half h, m; split2(v, h, m);
        size_t o = ((size_t)p*CMID + co)*CIN + c;
        g_Ws[o] = h;
        g_Ws[(size_t)9*CMID*CIN + o] = m;
    }
}

// ---------------- zero padded border rows of g_X + reset counters ----------------
__global__ void tborder_kernel() {
    int idx = blockIdx.x*blockDim.x + threadIdx.x;
    if (idx == 0) { g_cnt[0] = 0u; g_cnt[1] = 0u; g_tile = 0u; }
    if (idx >= 516*512) return;
    int b = idx / 512, cu = idx % 512;
    int row;
    if (b < 130) row = b;
    else if (b < 260) row = 129*TPAD + (b - 130);
    else if (b < 388) row = (b - 260 + 1)*TPAD;
    else row = (b - 388 + 1)*TPAD + 129;
    uint32_t* T32 = reinterpret_cast<uint32_t*>(g_X);
#pragma unroll
    for (int s = 0; s < 2; s++)
        T32[((size_t)s*TROWS + row)*512 + cu] = 0u;
}

// ---------------- input transpose + split ----------------
__global__ void xsplit_kernel(const float* __restrict__ in) {
    __shared__ float t[32][33];
    int px0 = blockIdx.x << 5;
    int cc0 = blockIdx.y << 5;
    int tid = threadIdx.x;
    int tx = tid & 31, ty = tid >> 5;
#pragma unroll
    for (int i = 0; i < 4; i++) {
        int c = cc0 + ty + i*8;
        t[ty + i*8][tx] = in[(size_t)c*HW + px0 + tx];
    }
    __syncthreads();
    uint32_t* X32 = reinterpret_cast<uint32_t*>(g_X);
    const size_t SPLIT32 = (size_t)TROWS*CIN/2;
#pragma unroll
    for (int pass = 0; pass < 2; pass++) {
        int px_l = (tid >> 4) + (pass << 4);
        int cp2 = tid & 15;
        float v0 = t[cp2*2][px_l], v1 = t[cp2*2+1][px_l];
        __half h0, m0, h1, m1;
        split2(v0, h0, m0);
        split2(v1, h1, m1);
        int pix = px0 + px_l;
        int row = (pix >> 7) + 1;
        int col = (pix & 127) + 1;
        size_t o32 = (((size_t)(row*TPAD + col))*CIN + cc0)/2 + cp2;
        X32[o32] = pk(h0, h1);
        X32[SPLIT32 + o32] = pk(m0, m1);
    }
}

// ---------------- conv3x3: 128px x 32co tiles, fp16 split GEMM, 3-deep pipeline ----------------
__global__ __launch_bounds__(256, 2)
void conv3_mma_kernel(const float* __restrict__ bc) {
    extern __shared__ char smem[];
    const uint32_t sb0 = smem_u32(smem);
    __shared__ unsigned s_tile;
    __shared__ float bsm[32];

    const int tid = threadIdx.x;
    const int lane = tid & 31;
    const int wid = tid >> 5;
    const int wm = wid >> 1;          // 0..3 (pixel dim, 32 px each)
    const int wn = wid & 1;           // 0..1 (co dim, 16 co each)

    const uint32_t Aoff = (uint32_t)(((lane & 7) + ((lane >> 3) & 1)*8)*80 + (lane >> 4)*16);
    const uint32_t Boff = (uint32_t)(((lane & 7) + (lane >> 4)*8)*80 + ((lane >> 3) & 1)*16);

    const char* Xg = (const char*)g_X;
    const char* Wg = (const char*)g_Ws;

    while (true) {
        if (tid == 0) s_tile = atomicAdd(&g_tile, 1u);
        __syncthreads();
        unsigned t = s_tile;
        __syncthreads();
        if (t >= NTILES) break;
        const int y = (int)(t >> 4);
        const int tn = (int)(t & 15);
        const int con0 = tn << 5;

        if (tid < 32) bsm[tid] = bc[con0 + tid];

        float acc_hi[2][2][4];
        float acc_lo[2][2][4];
#pragma unroll
        for (int a = 0; a < 2; a++)
#pragma unroll
            for (int b = 0; b < 2; b++)
#pragma unroll
                for (int c = 0; c < 4; c++) { acc_hi[a][b][c] = 0.f; acc_lo[a][b][c] = 0.f; }

        auto load_stage = [&](int s) {
            int ky = s >> 5, chunk = s & 31;
            int c0b = chunk << 6;
            int r0 = (y + ky)*TPAD;
            uint32_t buf = sb0 + (uint32_t)(s % NBUF)*STAGE_SZ;
            for (int i = tid; i < 1040; i += 256) {
                int sa = (i >= 520) ? 1 : 0;
                int j = i - sa*520;
                int row = j >> 2, q = j & 3;
                const char* src = Xg + (((size_t)sa*TROWS + r0 + row) << 11) + c0b + (q << 4);
                cp16(buf + sa*10400 + row*80 + (q << 4), src);
            }
#pragma unroll
            for (int it = 0; it < 3; it++) {
                int i = tid + it*256;
                int kx = i >> 8;
                int j = i & 255;
                int sbp = j >> 7;
                int jj = j & 127;
                int row = jj >> 2, q = jj & 3;
                int tap = ky*3 + kx;
                const char* src = Wg + ((((size_t)sbp*9 + tap)*CMID + con0 + row) << 11) + c0b + (q << 4);
                cp16(buf + ABUF_SZ + kx*5120 + sbp*2560 + row*80 + (q << 4), src);
            }
            asm volatile("cp.async.commit_group;" ::: "memory");
        };

        // prime 2 stages
        load_stage(0);
        load_stage(1);
        for (int s = 0; s < NSTAGES; s++) {
            if (s + 2 < NSTAGES) {
                load_stage(s + 2);
                asm volatile("cp.async.wait_group 2;" ::: "memory");
            } else if (s + 1 < NSTAGES) {
                asm volatile("cp.async.wait_group 1;" ::: "memory");
            } else {
                asm volatile("cp.async.wait_group 0;" ::: "memory");
            }
            __syncthreads();

            const uint32_t bufA = sb0 + (uint32_t)(s % NBUF)*STAGE_SZ;
            const uint32_t bufB = bufA + ABUF_SZ;

#pragma unroll
            for (int kx = 0; kx < 3; kx++) {
                const uint32_t aBase = bufA + (uint32_t)(kx + wm*32)*80 + Aoff;
                const uint32_t bBase = bufB + (uint32_t)kx*5120 + (uint32_t)(wn*16)*80 + Boff;
#pragma unroll
                for (int ks = 0; ks < 2; ks++) {
                    uint32_t bq0[4], bq1[4], aq[8];
                    ldsm4(bq0, bBase + ks*32);
                    ldsm4(bq1, bBase + 2560 + ks*32);
                    ldsm4(&aq[0], aBase + ks*32);
                    ldsm4(&aq[4], aBase + 16*80 + ks*32);
#pragma unroll
                    for (int mi = 0; mi < 2; mi++)
#pragma unroll
                        for (int ni = 0; ni < 2; ni++) {
                            mma16816(acc_hi[mi][ni], &aq[mi*4], &bq0[ni*2]);
                            mma16816(acc_lo[mi][ni], &aq[mi*4], &bq1[ni*2]);
                        }
                    ldsm4(&aq[0], aBase + 10400 + ks*32);
                    ldsm4(&aq[4], aBase + 10400 + 16*80 + ks*32);
#pragma unroll
                    for (int mi = 0; mi < 2; mi++)
#pragma unroll
                        for (int ni = 0; ni < 2; ni++)
                            mma16816(acc_lo[mi][ni], &aq[mi*4], &bq0[ni*2]);
                }
            }
            __syncthreads();
        }

        // ---- epilogue: relu(hi + lo/2048 + bias) -> g_conv1 ----
        const float INV2048 = 1.f/2048.f;
#pragma unroll
        for (int mi = 0; mi < 2; mi++)
#pragma unroll
            for (int ni = 0; ni < 2; ni++)
#pragma unroll
                for (int c = 0; c < 4; c++) {
                    int co = con0 + (wn << 4) + (ni << 3) + ((lane & 3) << 1) + (c & 1);
                    int px = (wm << 5) + (mi << 4) + (lane >> 2) + ((c >> 1) << 3);
                    float v = (acc_hi[mi][ni][c] + acc_lo[mi][ni][c]*INV2048) + bsm[co - con0];
                    g_conv1[(size_t)co*HW + (y << 7) + px] = fmaxf(v, 0.f);
                }
        __syncthreads();
    }
}

// ---------------- fused 1x1 convs + softmax + box decode (+ radix hist pass 1) ----------------
__global__ __launch_bounds__(256)
void conv1x1_decode_kernel(const float* __restrict__ Wcls, const float* __restrict__ bcls,
                           const float* __restrict__ Wbb,  const float* __restrict__ bbb,
                           const float* __restrict__ meta,
                           float* __restrict__ outP, float* __restrict__ outB) {
    extern __shared__ float dyn[];
    float* wsm = dyn;                       // [30][512]
    float* psm = dyn + 30*512;              // [4][64][30]
    float* osm = dyn + 30*512 + 4*64*30;    // [64][30]
    int tid = threadIdx.x;
    for (int i = tid; i < 30*512; i += 256) {
        int ch = i >> 9, c = i & 511;
        wsm[i] = (ch < 6) ? Wcls[ch*512 + c] : Wbb[(ch - 6)*512 + c];
    }
    __syncthreads();
    int q = tid >> 6, pxl = tid & 63;
    int px0 = blockIdx.x << 6;
    int px = px0 + pxl;
    float acc[30];
#pragma unroll
    for (int ch = 0; ch < 30; ch++) acc[ch] = 0.f;
    for (int cc = 0; cc < 128; cc++) {
        int c = (q << 7) + cc;
        float v = g_conv1[(size_t)c*HW + px];
#pragma unroll
        for (int ch = 0; ch < 30; ch++) acc[ch] += v * wsm[(ch << 9) + c];
    }
#pragma unroll
    for (int ch = 0; ch < 30; ch++) psm[(q*64 + pxl)*30 + ch] = acc[ch];
    __syncthreads();
    for (int i = tid; i < 64*30; i += 256) {
        int pl = i / 30, ch = i % 30;
        float s = psm[pl*30 + ch] + psm[(64 + pl)*30 + ch]
                + psm[(128 + pl)*30 + ch] + psm[(192 + pl)*30 + ch];
        float v;
        if (ch < 6) v = s + bcls[ch];
        else { v = s + bbb[ch - 6]; outB[(ch - 6)*HW + px0 + pl] = v; }
        osm[pl*30 + ch] = v;
    }
    __syncthreads();
    float im_h = meta[0], im_w = meta[1];
    for (int i = tid; i < 64*6; i += 256) {
        int pl = i / 6, a = i % 6;
        int pix = px0 + pl;
        float ss = osm[pl*30 + a];
        int ao = (a < 3) ? a + 3 : a - 3;
        float so = osm[pl*30 + ao];
        float m = fmaxf(ss, so);
        float e1 = expf(ss - m), e2 = expf(so - m);
        float p = e1 / (e1 + e2);
        outP[a*HW + pix] = p;
        g_scores[pix*6 + a] = p;
        atomicAdd(&g_hist[__float_as_uint(p) >> 20], 1u);

        float dims = c_dims[a];
        int x = pix & 127, yv = pix >> 7;
        float cxa = ((float)x + 0.5f) * 16.f;
        float cya = ((float)yv + 0.5f) * 16.f;
        float d0 = osm[pl*30 + 6 + a*4 + 0];
        float d1 = osm[pl*30 + 6 + a*4 + 1];
        float d2 = osm[pl*30 + 6 + a*4 + 2];
        float d3 = osm[pl*30 + 6 + a*4 + 3];
        float pcx = d0*dims + cxa;
        float pcy = d1*dims + cya;
        float pw  = expf(d2)*dims;
        float ph  = expf(d3)*dims;
        float bx1 = fminf(fmaxf(pcx - 0.5f*pw, 0.f), im_w);
        float by1 = fminf(fmaxf(pcy - 0.5f*ph, 0.f), im_h);
        float bx2 = fminf(fmaxf(pcx + 0.5f*pw, 0.f), im_w);
        float by2 = fminf(fmaxf(pcy + 0.5f*ph, 0.f), im_h);
        *reinterpret_cast<float4*>(&g_boxes[(pix*6 + a)*4]) = make_float4(bx1, by1, bx2, by2);
    }
}

// ---------------- radix select ----------------
__global__ void hist_kernel(int pass) {
    int i = blockIdx.x*blockDim.x + threadIdx.x;
    if (i >= NANCH) return;
    unsigned bits = __float_as_uint(g_scores[i]);
    if (pass == 2) {
        if ((bits >> 20) == g_state[0]) atomicAdd(&g_hist[(bits >> 8) & 0xFFFu], 1u);
    } else {
        if ((bits >> 8) == ((g_state[0] << 12) | g_state[2])) atomicAdd(&g_hist[bits & 0xFFu], 1u);
    }
}

__global__ void sel_kernel(int pass) {
    __shared__ unsigned sa[4096], sbv[4096];
    int tid = threadIdx.x;
    int nbins = (pass == 3) ? 256 : 4096;
    for (int i = tid; i < 4096; i += 1024) {
        sa[i] = (i < nbins) ? g_hist[i] : 0u;
        g_hist[i] = 0u;
    }
    __syncthreads();
    unsigned *src = sa, *dst = sbv;
    for (int off = 1; off < 4096; off <<= 1) {
        for (int i = tid; i < 4096; i += 1024)
            dst[i] = src[i] + ((i + off < 4096) ? src[i + off] : 0u);
        __syncthreads();
        unsigned* tp = src; src = dst; dst = tp;
    }
    unsigned need = (pass == 1) ? (unsigned)PRE_N : (pass == 2 ? g_state[1] : g_state[3]);
    for (int i = tid; i < nbins; i += 1024) {
        unsigned cg = (i + 1 < 4096) ? src[i + 1] : 0u;
        unsigned ci = src[i];
        if (ci >= need && cg < need) {
            if (pass == 1)      { g_state[0] = (unsigned)i; g_state[1] = need - cg; }
            else if (pass == 2) { g_state[2] = (unsigned)i; g_state[3] = need - cg; }
            else {
                g_state[4] = (g_state[0] << 20) | (g_state[2] << 8) | (unsigned)i;
                g_state[5] = need - cg;
            }
        }
    }
}

__global__ void compact_kernel() {
    int i = blockIdx.x*blockDim.x + threadIdx.x;
    if (i >= NANCH) return;
    unsigned bits = __float_as_uint(g_scores[i]);
    unsigned thr = g_state[4];
    if (bits > thr) {
        unsigned p = atomicAdd(&g_cnt[0], 1u);
        if (p < PRE_N + 256) g_great[p] = i;
    } else if (bits == thr) {
        unsigned p = atomicAdd(&g_cnt[1], 1u);
        if (p < 2048) g_tie[p] = i;
    }
}

// ---------------- sort-based finalize ----------------
__global__ void sortsel_kernel() {
    extern __shared__ unsigned long long keys[];   // 8192
    int tid = threadIdx.x;
    unsigned nG = min(g_cnt[0], (unsigned)PRE_N);
    unsigned nT = min(g_cnt[1], 2048u);
    unsigned total = nG + nT;
    for (int i = tid; i < 8192; i += 1024) {
        unsigned long long k = 0xFFFFFFFFFFFFFFFFull;
        if (i < (int)total) {
            int idx = (i < (int)nG) ? g_great[i] : g_tie[i - nG];
            unsigned bits = __float_as_uint(g_scores[idx]);
            k = ((unsigned long long)(~bits) << 32) | (unsigned)idx;
        }
        keys[i] = k;
    }
    __syncthreads();
    for (int k2 = 2; k2 <= 8192; k2 <<= 1) {
        for (int j = k2 >> 1; j > 0; j >>= 1) {
            for (int i = tid; i < 8192; i += 1024) {
                int ixj = i ^ j;
                if (ixj > i) {
                    bool up = ((i & k2) == 0);
                    unsigned long long a = keys[i], b = keys[ixj];
                    if ((a > b) == up) { keys[i] = b; keys[ixj] = a; }
                }
            }
            __syncthreads();
        }
    }
    for (int s2 = tid; s2 < PRE_N; s2 += 1024) {
        int idx = (int)(keys[s2] & 0xFFFFFFFFull);
        g_sel[s2] = idx;
        float4 bx = *reinterpret_cast<const float4*>(&g_boxes[idx*4]);
        *reinterpret_cast<float4*>(&g_selbox[s2*4]) = bx;
        g_selscore[s2] = g_scores[idx];
    }
}

// ---------------- greedy NMS (cached per-warp maxima, 2 barriers/iter) ----------------
__global__ void nms_kernel(float* __restrict__ rois) {
    extern __shared__ float sm[];
    float* X1 = sm;
    float* Y1 = sm + PRE_N;
    float* X2 = sm + 2*PRE_N;
    float* Y2 = sm + 3*PRE_N;
    float* AR = sm + 4*PRE_N;
    int*   KEEP = (int*)(sm + 5*PRE_N);
    __shared__ unsigned long long wmax[32];
    __shared__ float bb[6];

    int tid = threadIdx.x;
    int lane = tid & 31, wid = tid >> 5;
    float ms[6];
#pragma unroll
    for (int k = 0; k < 6; k++) {
        int i = tid + (k << 10);
        ms[k] = (i < PRE_N) ? g_selscore[i] : -1.f;
    }
    for (int i = tid; i < PRE_N; i += 1024) {
        float x1 = g_selbox[i*4+0], y1 = g_selbox[i*4+1];
        float x2 = g_selbox[i*4+2], y2 = g_selbox[i*4+3];
        X1[i] = x1; Y1[i] = y1; X2[i] = x2; Y2[i] = y2;
        AR[i] = fmaxf(x2 - x1, 0.f) * fmaxf(y2 - y1, 0.f);
    }
    bool dirty = true;
    __syncthreads();

    for (int it = 0; it < POST_N; it++) {
        if (dirty) {
            unsigned long long best = 0ull;
#pragma unroll
            for (int k = 0; k < 6; k++) {
                float v = ms[k];
                if (v >= 0.f) {
                    int i = tid + (k << 10);
                    unsigned long long kk = ((unsigned long long)__float_as_uint(v) << 32)
                                          | (unsigned)(0xFFFFFFFFu - (unsigned)i);
                    if (kk > best) best = kk;
                }
            }
#pragma unroll
            for (int off = 16; off > 0; off >>= 1) {
                unsigned long long o = __shfl_down_sync(0xffffffffu, best, off);
                if (o > best) best = o;
            }
            if (lane == 0) wmax[wid] = best;
        }
        __syncthreads();
        if (wid == 0) {
            unsigned long long b = wmax[lane];
#pragma unroll
            for (int off = 16; off > 0; off >>= 1) {
                unsigned long long o = __shfl_down_sync(0xffffffffu, b, off);
                if (o > b) b = o;
            }
            if (lane == 0) {
                bool valid = (b != 0ull);
                int j = valid ? (int)(0xFFFFFFFFu - (unsigned)(b & 0xFFFFFFFFull)) : 0;
                KEEP[it] = valid ? j : -1;
                bb[0] = X1[j]; bb[1] = Y1[j]; bb[2] = X2[j]; bb[3] = Y2[j];
                bb[4] = AR[j]; bb[5] = valid ? 1.f : 0.f;
            }
        }
        __syncthreads();
        bool changed = false;
        if (bb[5] > 0.f) {
            float bx1 = bb[0], by1 = bb[1], bx2 = bb[2], by2 = bb[3], ba = bb[4];
#pragma unroll
            for (int k = 0; k < 6; k++) {
                if (ms[k] >= 0.f) {
                    int i = tid + (k << 10);
                    float iw = fmaxf(fminf(X2[i], bx2) - fmaxf(X1[i], bx1), 0.f);
                    float ih = fmaxf(fminf(Y2[i], by2) - fmaxf(Y1[i], by1), 0.f);
                    float inter = iw * ih;
                    float iou = inter / (AR[i] + ba - inter + 1e-9f);
                    if (iou > 0.7f) { ms[k] = -1.f; changed = true; }
                }
            }
        }
        dirty = (__ballot_sync(0xffffffffu, changed) != 0u);
    }

    __syncthreads();
    if (tid < POST_N) {
        int j = KEEP[tid];
        float* o = rois + tid*5;
        if (j >= 0) { o[0] = 0.f; o[1] = X1[j]; o[2] = Y1[j]; o[3] = X2[j]; o[4] = Y2[j]; }
        else        { o[0] = 0.f; o[1] = 0.f;  o[2] = 0.f;  o[3] = 0.f;  o[4] = 0.f; }
    }
}

// ---------------- launch ----------------
extern "C" void kernel_launch(void* const* d_in, const int* in_sizes, int n_in,
                              void* d_out, int out_size) {
    const float* base = (const float*)d_in[0];
    const float* meta = (const float*)d_in[1];
    const float* Wc   = (const float*)d_in[3];
    const float* bc   = (const float*)d_in[4];
    const float* Wcls = (const float*)d_in[5];
    const float* bcls = (const float*)d_in[6];
    const float* Wbb  = (const float*)d_in[7];
    const float* bbb  = (const float*)d_in[8];

    float* out  = (float*)d_out;
    float* outP = out + POST_N*5;
    float* outB = outP + NA*HW;

    const int C1X1_SMEM = (30*512 + 4*64*30 + 64*30) * 4;   // 99840
    cudaFuncSetAttribute(conv3_mma_kernel,      cudaFuncAttributeMaxDynamicSharedMemorySize, SMEM_SZ);
    cudaFuncSetAttribute(conv1x1_decode_kernel, cudaFuncAttributeMaxDynamicSharedMemorySize, C1X1_SMEM);
    cudaFuncSetAttribute(sortsel_kernel,        cudaFuncAttributeMaxDynamicSharedMemorySize, 65536);
    cudaFuncSetAttribute(nms_kernel,            cudaFuncAttributeMaxDynamicSharedMemorySize, 140000);

    wsplit_kernel<<<(CMID*CIN + 255)/256, 256>>>(Wc);
    tborder_kernel<<<(516*512 + 255)/256, 256>>>();
    xsplit_kernel<<<dim3(HW/32, CIN/32), 256>>>(base);
    conv3_mma_kernel<<<304, 256, SMEM_SZ>>>(bc);
    conv1x1_decode_kernel<<<256, 256, C1X1_SMEM>>>(Wcls, bcls, Wbb, bbb, meta, outP, outB);
    sel_kernel<<<1, 1024>>>(1);
    hist_kernel<<<NANCH/256, 256>>>(2);
    sel_kernel<<<1, 1024>>>(2);
    hist_kernel<<<NANCH/256, 256>>>(3);
    sel_kernel<<<1, 1024>>>(3);
    compact_kernel<<<NANCH/256, 256>>>();
    sortsel_kernel<<<1, 1024, 65536>>>();
    nms_kernel<<<1, 1024, (5*PRE_N + 512) * 4>>>(out);
}

// round 16
// speedup vs baseline: 1.1355x; 1.1355x over previous
#include <cuda_runtime.h>
#include <cuda_fp16.h>
#include <math.h>
#include <stdint.h>

#define HH 128
#define WW 128
#define CIN 1024
#define CMID 512
#define NA 6
#define HW (HH*WW)
#define NANCH (HW*NA)
#define PRE_N 6000
#define POST_N 300
#define KTOT 9216
#define TPAD 130
#define TROWS (TPAD*TPAD)   // 16900
#define NTILES 2048         // 128 rows x 16 co-tiles(32)
#define NSTAGES 96          // 3 ky x 32 chunks of 32 channels

// smem per buffer: A 2 splits x (130 rows x 80B) = 20800, B 3 kx x 2 splits x (32 x 80B) = 15360
#define ABUF_SZ 20800
#define STAGE_SZ 36160
#define SMEM_SZ  (2*STAGE_SZ)   // 72320

// ---------------- device scratch ----------------
__device__ __align__(16) __half g_X[2u*TROWS*CIN];       // padded input splits [s][row][c]
__device__ __align__(16) __half g_Ws[2u*9*CMID*CIN];     // weight splits [s][tap][co][c]
__device__ __align__(16) float g_conv1[CMID*HW];
__device__ unsigned int g_tile;
__device__ float g_boxes[NANCH*4];
__device__ float g_scores[NANCH];
__device__ unsigned int g_hist[4096];
__device__ unsigned int g_state[8];
__device__ unsigned int g_cnt[2];
__device__ int g_great[PRE_N + 256];
__device__ int g_tie[2048];
__device__ int g_sel[PRE_N];
__device__ float g_selbox[PRE_N*4];
__device__ float g_selscore[PRE_N];

__constant__ float c_dims[NA] = {16.f, 32.f, 64.f, 128.f, 256.f, 512.f};

// ---------------- helpers ----------------
__device__ __forceinline__ uint32_t smem_u32(const void* p) {
    uint32_t a;
    asm("{ .reg .u64 t; cvta.to.shared.u64 t, %1; cvt.u32.u64 %0, t; }" : "=r"(a) : "l"(p));
    return a;
}
__device__ __forceinline__ void cp16(uint32_t dst, const void* src) {
    asm volatile("cp.async.cg.shared.global [%0], [%1], 16;" :: "r"(dst), "l"(src) : "memory");
}
__device__ __forceinline__ void ldsm4(uint32_t* r, uint32_t addr) {
    asm volatile("ldmatrix.sync.aligned.m8n8.x4.shared.b16 {%0,%1,%2,%3}, [%4];"
        : "=r"(r[0]), "=r"(r[1]), "=r"(r[2]), "=r"(r[3]) : "r"(addr));
}
__device__ __forceinline__ void mma16816(float* d, const uint32_t* a, const uint32_t* b) {
    asm volatile("mma.sync.aligned.m16n8k16.row.col.f32.f16.f16.f32 "
        "{%0,%1,%2,%3}, {%4,%5,%6,%7}, {%8,%9}, {%0,%1,%2,%3};"
        : "+f"(d[0]), "+f"(d[1]), "+f"(d[2]), "+f"(d[3])
        : "r"(a[0]), "r"(a[1]), "r"(a[2]), "r"(a[3]), "r"(b[0]), "r"(b[1]));
}
// fp16 scaled 2-way split: v = h + m/2048
__device__ __forceinline__ void split2(float v, __half& h, __half& m) {
    h = __float2half(v);
    float r = v - __half2float(h);
    m = __float2half(r * 2048.f);
}
__device__ __forceinline__ uint32_t pk(__half a, __half b) {
    unsigned short x = *(unsigned short*)&a, y = *(unsigned short*)&b;
    return (uint32_t)x | ((uint32_t)y << 16);
}

// ---------------- weight split ----------------
__global__ void wsplit_kernel(const float* __restrict__ Wc) {
    int idx = blockIdx.x*blockDim.x + threadIdx.x;
    if (idx >= CMID*CIN) return;
    int co = idx >> 10, c = idx & 1023;
#pragma unroll
    for (int p = 0; p < 9; p++) {
        float v = Wc[(size_t)co*KTOT + c*9 + p];
        __half h, m; split2(v, h, m);
        size_t o = ((size_t)p*CMID + co)*CIN + c;
        g_Ws[o] = h;
        g_Ws[(size_t)9*CMID*CIN + o] = m;
    }
}

// ---------------- zero padded border rows of g_X + reset counters ----------------
__global__ void tborder_kernel() {
    int idx = blockIdx.x*blockDim.x + threadIdx.x;
    if (idx == 0) { g_cnt[0] = 0u; g_cnt[1] = 0u; g_tile = 0u; }
    if (idx >= 516*512) return;
    int b = idx / 512, cu = idx % 512;
    int row;
    if (b < 130) row = b;
    else if (b < 260) row = 129*TPAD + (b - 130);
    else if (b < 388) row = (b - 260 + 1)*TPAD;
    else row = (b - 388 + 1)*TPAD + 129;
    uint32_t* T32 = reinterpret_cast<uint32_t*>(g_X);
#pragma unroll
    for (int s = 0; s < 2; s++)
        T32[((size_t)s*TROWS + row)*512 + cu] = 0u;
}

// ---------------- input transpose + split ----------------
__global__ void xsplit_kernel(const float* __restrict__ in) {
    __shared__ float t[32][33];
    int px0 = blockIdx.x << 5;
    int cc0 = blockIdx.y << 5;
    int tid = threadIdx.x;
    int tx = tid & 31, ty = tid >> 5;
#pragma unroll
    for (int i = 0; i < 4; i++) {
        int c = cc0 + ty + i*8;
        t[ty + i*8][tx] = in[(size_t)c*HW + px0 + tx];
    }
    __syncthreads();
    uint32_t* X32 = reinterpret_cast<uint32_t*>(g_X);
    const size_t SPLIT32 = (size_t)TROWS*CIN/2;
#pragma unroll
    for (int pass = 0; pass < 2; pass++) {
        int px_l = (tid >> 4) + (pass << 4);
        int cp2 = tid & 15;
        float v0 = t[cp2*2][px_l], v1 = t[cp2*2+1][px_l];
        __half h0, m0, h1, m1;
        split2(v0, h0, m0);
        split2(v1, h1, m1);
        int pix = px0 + px_l;
        int row = (pix >> 7) + 1;
        int col = (pix & 127) + 1;
        size_t o32 = (((size_t)(row*TPAD + col))*CIN + cc0)/2 + cp2;
        X32[o32] = pk(h0, h1);
        X32[SPLIT32 + o32] = pk(m0, m1);
    }
}

// ---------------- conv3x3: 128px x 32co tiles, fp16 split GEMM, A shared across kx ----------------
__global__ __launch_bounds__(256, 3)
void conv3_mma_kernel(const float* __restrict__ bc) {
    extern __shared__ char smem[];
    const uint32_t sb0 = smem_u32(smem);
    __shared__ unsigned s_tile;
    __shared__ float bsm[32];

    const int tid = threadIdx.x;
    const int lane = tid & 31;
    const int wid = tid >> 5;
    const int wm = wid >> 1;          // 0..3 (pixel dim, 32 px each)
    const int wn = wid & 1;           // 0..1 (co dim, 16 co each)

    const uint32_t Aoff = (uint32_t)(((lane & 7) + ((lane >> 3) & 1)*8)*80 + (lane >> 4)*16);
    const uint32_t Boff = (uint32_t)(((lane & 7) + (lane >> 4)*8)*80 + ((lane >> 3) & 1)*16);

    const char* Xg = (const char*)g_X;
    const char* Wg = (const char*)g_Ws;

    while (true) {
        if (tid == 0) s_tile = atomicAdd(&g_tile, 1u);
        __syncthreads();
        unsigned t = s_tile;
        __syncthreads();
        if (t >= NTILES) break;
        const int y = (int)(t >> 4);
        const int tn = (int)(t & 15);
        const int con0 = tn << 5;

        if (tid < 32) bsm[tid] = bc[con0 + tid];

        float acc_hi[2][2][4];
        float acc_lo[2][2][4];
#pragma unroll
        for (int a = 0; a < 2; a++)
#pragma unroll
            for (int b = 0; b < 2; b++)
#pragma unroll
                for (int c = 0; c < 4; c++) { acc_hi[a][b][c] = 0.f; acc_lo[a][b][c] = 0.f; }

        auto load_stage = [&](int s) {
            int ky = s >> 5, chunk = s & 31;
            int c0b = chunk << 6;
            int r0 = (y + ky)*TPAD;
            uint32_t buf = sb0 + (uint32_t)(s & 1)*STAGE_SZ;
            for (int i = tid; i < 1040; i += 256) {
                int sa = (i >= 520) ? 1 : 0;
                int j = i - sa*520;
                int row = j >> 2, q = j & 3;
                const char* src = Xg + (((size_t)sa*TROWS + r0 + row) << 11) + c0b + (q << 4);
                cp16(buf + sa*10400 + row*80 + (q << 4), src);
            }
#pragma unroll
            for (int it = 0; it < 3; it++) {
                int i = tid + it*256;
                int kx = i >> 8;
                int j = i & 255;
                int sbp = j >> 7;
                int jj = j & 127;
                int row = jj >> 2, q = jj & 3;
                int tap = ky*3 + kx;
                const char* src = Wg + ((((size_t)sbp*9 + tap)*CMID + con0 + row) << 11) + c0b + (q << 4);
                cp16(buf + ABUF_SZ + kx*5120 + sbp*2560 + row*80 + (q << 4), src);
            }
            asm volatile("cp.async.commit_group;" ::: "memory");
        };

        load_stage(0);
        for (int s = 0; s < NSTAGES; s++) {
            if (s + 1 < NSTAGES) {
                load_stage(s + 1);
                asm volatile("cp.async.wait_group 1;" ::: "memory");
            } else {
                asm volatile("cp.async.wait_group 0;" ::: "memory");
            }
            __syncthreads();

            const uint32_t bufA = sb0 + (uint32_t)(s & 1)*STAGE_SZ;
            const uint32_t bufB = bufA + ABUF_SZ;

#pragma unroll
            for (int kx = 0; kx < 3; kx++) {
                const uint32_t aBase = bufA + (uint32_t)(kx + wm*32)*80 + Aoff;
                const uint32_t bBase = bufB + (uint32_t)kx*5120 + (uint32_t)(wn*16)*80 + Boff;
#pragma unroll
                for (int ks = 0; ks < 2; ks++) {
                    uint32_t bq0[4], bq1[4], aq[8];
                    ldsm4(bq0, bBase + ks*32);
                    ldsm4(bq1, bBase + 2560 + ks*32);
                    ldsm4(&aq[0], aBase + ks*32);
                    ldsm4(&aq[4], aBase + 16*80 + ks*32);
#pragma unroll
                    for (int mi = 0; mi < 2; mi++)
#pragma unroll
                        for (int ni = 0; ni < 2; ni++) {
                            mma16816(acc_hi[mi][ni], &aq[mi*4], &bq0[ni*2]);
                            mma16816(acc_lo[mi][ni], &aq[mi*4], &bq1[ni*2]);
                        }
                    ldsm4(&aq[0], aBase + 10400 + ks*32);
                    ldsm4(&aq[4], aBase + 10400 + 16*80 + ks*32);
#pragma unroll
                    for (int mi = 0; mi < 2; mi++)
#pragma unroll
                        for (int ni = 0; ni < 2; ni++)
                            mma16816(acc_lo[mi][ni], &aq[mi*4], &bq0[ni*2]);
                }
            }
            __syncthreads();
        }

        // ---- epilogue: relu(hi + lo/2048 + bias) -> g_conv1 ----
        const float INV2048 = 1.f/2048.f;
#pragma unroll
        for (int mi = 0; mi < 2; mi++)
#pragma unroll
            for (int ni = 0; ni < 2; ni++)
#pragma unroll
                for (int c = 0; c < 4; c++) {
                    int co = con0 + (wn << 4) + (ni << 3) + ((lane & 3) << 1) + (c & 1);
                    int px = (wm << 5) + (mi << 4) + (lane >> 2) + ((c >> 1) << 3);
                    float v = (acc_hi[mi][ni][c] + acc_lo[mi][ni][c]*INV2048) + bsm[co - con0];
                    g_conv1[(size_t)co*HW + (y << 7) + px] = fmaxf(v, 0.f);
                }
        __syncthreads();
    }
}

// ---------------- fused 1x1 convs + softmax + box decode (+ radix hist pass 1) ----------------
__global__ __launch_bounds__(256)
void conv1x1_decode_kernel(const float* __restrict__ Wcls, const float* __restrict__ bcls,
                           const float* __restrict__ Wbb,  const float* __restrict__ bbb,
                           const float* __restrict__ meta,
                           float* __restrict__ outP, float* __restrict__ outB) {
    extern __shared__ float dyn[];
    float* wsm = dyn;                       // [30][512]
    float* psm = dyn + 30*512;              // [4][64][30]
    float* osm = dyn + 30*512 + 4*64*30;    // [64][30]
    int tid = threadIdx.x;
    for (int i = tid; i < 30*512; i += 256) {
        int ch = i >> 9, c = i & 511;
        wsm[i] = (ch < 6) ? Wcls[ch*512 + c] : Wbb[(ch - 6)*512 + c];
    }
    __syncthreads();
    int q = tid >> 6, pxl = tid & 63;
    int px0 = blockIdx.x << 6;
    int px = px0 + pxl;
    float acc[30];
#pragma unroll
    for (int ch = 0; ch < 30; ch++) acc[ch] = 0.f;
    for (int cc = 0; cc < 128; cc++) {
        int c = (q << 7) + cc;
        float v = g_conv1[(size_t)c*HW + px];
#pragma unroll
        for (int ch = 0; ch < 30; ch++) acc[ch] += v * wsm[(ch << 9) + c];
    }
#pragma unroll
    for (int ch = 0; ch < 30; ch++) psm[(q*64 + pxl)*30 + ch] = acc[ch];
    __syncthreads();
    for (int i = tid; i < 64*30; i += 256) {
        int pl = i / 30, ch = i % 30;
        float s = psm[pl*30 + ch] + psm[(64 + pl)*30 + ch]
                + psm[(128 + pl)*30 + ch] + psm[(192 + pl)*30 + ch];
        float v;
        if (ch < 6) v = s + bcls[ch];
        else { v = s + bbb[ch - 6]; outB[(ch - 6)*HW + px0 + pl] = v; }
        osm[pl*30 + ch] = v;
    }
    __syncthreads();
    float im_h = meta[0], im_w = meta[1];
    for (int i = tid; i < 64*6; i += 256) {
        int pl = i / 6, a = i % 6;
        int pix = px0 + pl;
        float ss = osm[pl*30 + a];
        int ao = (a < 3) ? a + 3 : a - 3;
        float so = osm[pl*30 + ao];
        float m = fmaxf(ss, so);
        float e1 = expf(ss - m), e2 = expf(so - m);
        float p = e1 / (e1 + e2);
        outP[a*HW + pix] = p;
        g_scores[pix*6 + a] = p;
        atomicAdd(&g_hist[__float_as_uint(p) >> 20], 1u);

        float dims = c_dims[a];
        int x = pix & 127, yv = pix >> 7;
        float cxa = ((float)x + 0.5f) * 16.f;
        float cya = ((float)yv + 0.5f) * 16.f;
        float d0 = osm[pl*30 + 6 + a*4 + 0];
        float d1 = osm[pl*30 + 6 + a*4 + 1];
        float d2 = osm[pl*30 + 6 + a*4 + 2];
        float d3 = osm[pl*30 + 6 + a*4 + 3];
        float pcx = d0*dims + cxa;
        float pcy = d1*dims + cya;
        float pw  = expf(d2)*dims;
        float ph  = expf(d3)*dims;
        float bx1 = fminf(fmaxf(pcx - 0.5f*pw, 0.f), im_w);
        float by1 = fminf(fmaxf(pcy - 0.5f*ph, 0.f), im_h);
        float bx2 = fminf(fmaxf(pcx + 0.5f*pw, 0.f), im_w);
        float by2 = fminf(fmaxf(pcy + 0.5f*ph, 0.f), im_h);
        *reinterpret_cast<float4*>(&g_boxes[(pix*6 + a)*4]) = make_float4(bx1, by1, bx2, by2);
    }
}

// ---------------- radix select ----------------
__global__ void hist_kernel(int pass) {
    int i = blockIdx.x*blockDim.x + threadIdx.x;
    if (i >= NANCH) return;
    unsigned bits = __float_as_uint(g_scores[i]);
    if (pass == 2) {
        if ((bits >> 20) == g_state[0]) atomicAdd(&g_hist[(bits >> 8) & 0xFFFu], 1u);
    } else {
        if ((bits >> 8) == ((g_state[0] << 12) | g_state[2])) atomicAdd(&g_hist[bits & 0xFFu], 1u);
    }
}

__global__ void sel_kernel(int pass) {
    __shared__ unsigned sa[4096], sbv[4096];
    int tid = threadIdx.x;
    int nbins = (pass == 3) ? 256 : 4096;
    for (int i = tid; i < 4096; i += 1024) {
        sa[i] = (i < nbins) ? g_hist[i] : 0u;
        g_hist[i] = 0u;
    }
    __syncthreads();
    unsigned *src = sa, *dst = sbv;
    for (int off = 1; off < 4096; off <<= 1) {
        for (int i = tid; i < 4096; i += 1024)
            dst[i] = src[i] + ((i + off < 4096) ? src[i + off] : 0u);
        __syncthreads();
        unsigned* tp = src; src = dst; dst = tp;
    }
    unsigned need = (pass == 1) ? (unsigned)PRE_N : (pass == 2 ? g_state[1] : g_state[3]);
    for (int i = tid; i < nbins; i += 1024) {
        unsigned cg = (i + 1 < 4096) ? src[i + 1] : 0u;
        unsigned ci = src[i];
        if (ci >= need && cg < need) {
            if (pass == 1)      { g_state[0] = (unsigned)i; g_state[1] = need - cg; }
            else if (pass == 2) { g_state[2] = (unsigned)i; g_state[3] = need - cg; }
            else {
                g_state[4] = (g_state[0] << 20) | (g_state[2] << 8) | (unsigned)i;
                g_state[5] = need - cg;
            }
        }
    }
}

__global__ void compact_kernel() {
    int i = blockIdx.x*blockDim.x + threadIdx.x;
    if (i >= NANCH) return;
    unsigned bits = __float_as_uint(g_scores[i]);
    unsigned thr = g_state[4];
    if (bits > thr) {
        unsigned p = atomicAdd(&g_cnt[0], 1u);
        if (p < PRE_N + 256) g_great[p] = i;
    } else if (bits == thr) {
        unsigned p = atomicAdd(&g_cnt[1], 1u);
        if (p < 2048) g_tie[p] = i;
    }
}

// ---------------- sort-based finalize ----------------
__global__ void sortsel_kernel() {
    extern __shared__ unsigned long long keys[];   // 8192
    int tid = threadIdx.x;
    unsigned nG = min(g_cnt[0], (unsigned)PRE_N);
    unsigned nT = min(g_cnt[1], 2048u);
    unsigned total = nG + nT;
    for (int i = tid; i < 8192; i += 1024) {
        unsigned long long k = 0xFFFFFFFFFFFFFFFFull;
        if (i < (int)total) {
            int idx = (i < (int)nG) ? g_great[i] : g_tie[i - nG];
            unsigned bits = __float_as_uint(g_scores[idx]);
            k = ((unsigned long long)(~bits) << 32) | (unsigned)idx;
        }
        keys[i] = k;
    }
    __syncthreads();
    for (int k2 = 2; k2 <= 8192; k2 <<= 1) {
        for (int j = k2 >> 1; j > 0; j >>= 1) {
            for (int i = tid; i < 8192; i += 1024) {
                int ixj = i ^ j;
                if (ixj > i) {
                    bool up = ((i & k2) == 0);
                    unsigned long long a = keys[i], b = keys[ixj];
                    if ((a > b) == up) { keys[i] = b; keys[ixj] = a; }
                }
            }
            __syncthreads();
        }
    }
    for (int s2 = tid; s2 < PRE_N; s2 += 1024) {
        int idx = (int)(keys[s2] & 0xFFFFFFFFull);
        g_sel[s2] = idx;
        float4 bx = *reinterpret_cast<const float4*>(&g_boxes[idx*4]);
        *reinterpret_cast<float4*>(&g_selbox[s2*4]) = bx;
        g_selscore[s2] = g_scores[idx];
    }
}

// ---------------- greedy NMS (cached per-warp maxima, 2 barriers/iter) ----------------
__global__ void nms_kernel(float* __restrict__ rois) {
    extern __shared__ float sm[];
    float* X1 = sm;
    float* Y1 = sm + PRE_N;
    float* X2 = sm + 2*PRE_N;
    float* Y2 = sm + 3*PRE_N;
    float* AR = sm + 4*PRE_N;
    int*   KEEP = (int*)(sm + 5*PRE_N);
    __shared__ unsigned long long wmax[32];
    __shared__ float bb[6];

    int tid = threadIdx.x;
    int lane = tid & 31, wid = tid >> 5;
    float ms[6];
#pragma unroll
    for (int k = 0; k < 6; k++) {
        int i = tid + (k << 10);
        ms[k] = (i < PRE_N) ? g_selscore[i] : -1.f;
    }
    for (int i = tid; i < PRE_N; i += 1024) {
        float x1 = g_selbox[i*4+0], y1 = g_selbox[i*4+1];
        float x2 = g_selbox[i*4+2], y2 = g_selbox[i*4+3];
        X1[i] = x1; Y1[i] = y1; X2[i] = x2; Y2[i] = y2;
        AR[i] = fmaxf(x2 - x1, 0.f) * fmaxf(y2 - y1, 0.f);
    }
    bool dirty = true;
    __syncthreads();

    for (int it = 0; it < POST_N; it++) {
        if (dirty) {
            unsigned long long best = 0ull;
#pragma unroll
            for (int k = 0; k < 6; k++) {
                float v = ms[k];
                if (v >= 0.f) {
                    int i = tid + (k << 10);
                    unsigned long long kk = ((unsigned long long)__float_as_uint(v) << 32)
                                          | (unsigned)(0xFFFFFFFFu - (unsigned)i);
                    if (kk > best) best = kk;
                }
            }
#pragma unroll
            for (int off = 16; off > 0; off >>= 1) {
                unsigned long long o = __shfl_down_sync(0xffffffffu, best, off);
                if (o > best) best = o;
            }
            if (lane == 0) wmax[wid] = best;
        }
        __syncthreads();
        if (wid == 0) {
            unsigned long long b = wmax[lane];
#pragma unroll
            for (int off = 16; off > 0; off >>= 1) {
                unsigned long long o = __shfl_down_sync(0xffffffffu, b, off);
                if (o > b) b = o;
            }
            if (lane == 0) {
                bool valid = (b != 0ull);
                int j = valid ? (int)(0xFFFFFFFFu - (unsigned)(b & 0xFFFFFFFFull)) : 0;
                KEEP[it] = valid ? j : -1;
                bb[0] = X1[j]; bb[1] = Y1[j]; bb[2] = X2[j]; bb[3] = Y2[j];
                bb[4] = AR[j]; bb[5] = valid ? 1.f : 0.f;
            }
        }
        __syncthreads();
        bool changed = false;
        if (bb[5] > 0.f) {
            float bx1 = bb[0], by1 = bb[1], bx2 = bb[2], by2 = bb[3], ba = bb[4];
#pragma unroll
            for (int k = 0; k < 6; k++) {
                if (ms[k] >= 0.f) {
                    int i = tid + (k << 10);
                    float iw = fmaxf(fminf(X2[i], bx2) - fmaxf(X1[i], bx1), 0.f);
                    float ih = fmaxf(fminf(Y2[i], by2) - fmaxf(Y1[i], by1), 0.f);
                    float inter = iw * ih;
                    float iou = inter / (AR[i] + ba - inter + 1e-9f);
                    if (iou > 0.7f) { ms[k] = -1.f; changed = true; }
                }
            }
        }
        dirty = (__ballot_sync(0xffffffffu, changed) != 0u);
    }

    __syncthreads();
    if (tid < POST_N) {
        int j = KEEP[tid];
        float* o = rois + tid*5;
        if (j >= 0) { o[0] = 0.f; o[1] = X1[j]; o[2] = Y1[j]; o[3] = X2[j]; o[4] = Y2[j]; }
        else        { o[0] = 0.f; o[1] = 0.f;  o[2] = 0.f;  o[3] = 0.f;  o[4] = 0.f; }
    }
}

// ---------------- launch ----------------
extern "C" void kernel_launch(void* const* d_in, const int* in_sizes, int n_in,
                              void* d_out, int out_size) {
    const float* base = (const float*)d_in[0];
    const float* meta = (const float*)d_in[1];
    const float* Wc   = (const float*)d_in[3];
    const float* bc   = (const float*)d_in[4];
    const float* Wcls = (const float*)d_in[5];
    const float* bcls = (const float*)d_in[6];
    const float* Wbb  = (const float*)d_in[7];
    const float* bbb  = (const float*)d_in[8];

    float* out  = (float*)d_out;
    float* outP = out + POST_N*5;
    float* outB = outP + NA*HW;

    const int C1X1_SMEM = (30*512 + 4*64*30 + 64*30) * 4;   // 99840
    cudaFuncSetAttribute(conv3_mma_kernel,      cudaFuncAttributeMaxDynamicSharedMemorySize, SMEM_SZ);
    cudaFuncSetAttribute(conv1x1_decode_kernel, cudaFuncAttributeMaxDynamicSharedMemorySize, C1X1_SMEM);
    cudaFuncSetAttribute(sortsel_kernel,        cudaFuncAttributeMaxDynamicSharedMemorySize, 65536);
    cudaFuncSetAttribute(nms_kernel,            cudaFuncAttributeMaxDynamicSharedMemorySize, 140000);

    wsplit_kernel<<<(CMID*CIN + 255)/256, 256>>>(Wc);
    tborder_kernel<<<(516*512 + 255)/256, 256>>>();
    xsplit_kernel<<<dim3(HW/32, CIN/32), 256>>>(base);
    conv3_mma_kernel<<<456, 256, SMEM_SZ>>>(bc);
    conv1x1_decode_kernel<<<256, 256, C1X1_SMEM>>>(Wcls, bcls, Wbb, bbb, meta, outP, outB);
    sel_kernel<<<1, 1024>>>(1);
    hist_kernel<<<NANCH/256, 256>>>(2);
    sel_kernel<<<1, 1024>>>(2);
    hist_kernel<<<NANCH/256, 256>>>(3);
    sel_kernel<<<1, 1024>>>(3);
    compact_kernel<<<NANCH/256, 256>>>();
    sortsel_kernel<<<1, 1024, 65536>>>();
    nms_kernel<<<1, 1024, (5*PRE_N + 512) * 4>>>(out);
}

// round 17
// speedup vs baseline: 1.1405x; 1.0044x over previous
#include <cuda_runtime.h>
#include <cuda_fp16.h>
#include <math.h>
#include <stdint.h>

#define HH 128
#define WW 128
#define CIN 1024
#define CMID 512
#define NA 6
#define HW (HH*WW)
#define NANCH (HW*NA)
#define PRE_N 6000
#define POST_N 300
#define KTOT 9216
#define TPAD 130
#define TROWS (TPAD*TPAD)   // 16900
#define NTILES 2048         // 128 rows x 16 co-tiles(32)
#define NSTAGES 96          // 3 ky x 32 chunks of 32 channels

// smem per buffer: A 2 splits x (130 rows x 80B) = 20800, B 3 kx x 2 splits x (32 x 80B) = 15360
#define ABUF_SZ 20800
#define STAGE_SZ 36160
#define SMEM_SZ  (2*STAGE_SZ)   // 72320

// ---------------- device scratch ----------------
__device__ __align__(16) __half g_X[2u*TROWS*CIN];       // padded input splits [s][row][c]
__device__ __align__(16) __half g_Ws[2u*9*CMID*CIN];     // weight splits [s][tap][co][c]
__device__ __align__(16) float g_conv1[CMID*HW];
__device__ unsigned int g_tile;
__device__ float g_boxes[NANCH*4];
__device__ float g_scores[NANCH];
__device__ unsigned int g_hist[4096];
__device__ unsigned int g_state[8];
__device__ unsigned int g_cnt[2];
__device__ int g_great[PRE_N + 256];
__device__ int g_tie[4096];
__device__ int g_sel[PRE_N];
__device__ float g_selbox[PRE_N*4];
__device__ float g_selscore[PRE_N];

__constant__ float c_dims[NA] = {16.f, 32.f, 64.f, 128.f, 256.f, 512.f};

// ---------------- helpers ----------------
__device__ __forceinline__ uint32_t smem_u32(const void* p) {
    uint32_t a;
    asm("{ .reg .u64 t; cvta.to.shared.u64 t, %1; cvt.u32.u64 %0, t; }" : "=r"(a) : "l"(p));
    return a;
}
__device__ __forceinline__ void cp16(uint32_t dst, const void* src) {
    asm volatile("cp.async.cg.shared.global [%0], [%1], 16;" :: "r"(dst), "l"(src) : "memory");
}
__device__ __forceinline__ void ldsm4(uint32_t* r, uint32_t addr) {
    asm volatile("ldmatrix.sync.aligned.m8n8.x4.shared.b16 {%0,%1,%2,%3}, [%4];"
        : "=r"(r[0]), "=r"(r[1]), "=r"(r[2]), "=r"(r[3]) : "r"(addr));
}
__device__ __forceinline__ void mma16816(float* d, const uint32_t* a, const uint32_t* b) {
    asm volatile("mma.sync.aligned.m16n8k16.row.col.f32.f16.f16.f32 "
        "{%0,%1,%2,%3}, {%4,%5,%6,%7}, {%8,%9}, {%0,%1,%2,%3};"
        : "+f"(d[0]), "+f"(d[1]), "+f"(d[2]), "+f"(d[3])
        : "r"(a[0]), "r"(a[1]), "r"(a[2]), "r"(a[3]), "r"(b[0]), "r"(b[1]));
}
// fp16 scaled 2-way split: v = h + m/2048
__device__ __forceinline__ void split2(float v, __half& h, __half& m) {
    h = __float2half(v);
    float r = v - __half2float(h);
    m = __float2half(r * 2048.f);
}
__device__ __forceinline__ uint32_t pk(__half a, __half b) {
    unsigned short x = *(unsigned short*)&a, y = *(unsigned short*)&b;
    return (uint32_t)x | ((uint32_t)y << 16);
}

// ---------------- weight split ----------------
__global__ void wsplit_kernel(const float* __restrict__ Wc) {
    int idx = blockIdx.x*blockDim.x + threadIdx.x;
    if (idx >= CMID*CIN) return;
    int co = idx >> 10, c = idx & 1023;
#pragma unroll
    for (int p = 0; p < 9; p++) {
        float v = Wc[(size_t)co*KTOT + c*9 + p];
        __half h, m; split2(v, h, m);
        size_t o = ((size_t)p*CMID + co)*CIN + c;
        g_Ws[o] = h;
        g_Ws[(size_t)9*CMID*CIN + o] = m;
    }
}

// ---------------- zero padded border rows of g_X + reset counters ----------------
__global__ void tborder_kernel() {
    int idx = blockIdx.x*blockDim.x + threadIdx.x;
    if (idx == 0) { g_cnt[0] = 0u; g_cnt[1] = 0u; g_tile = 0u; }
    if (idx >= 516*512) return;
    int b = idx / 512, cu = idx % 512;
    int row;
    if (b < 130) row = b;
    else if (b < 260) row = 129*TPAD + (b - 130);
    else if (b < 388) row = (b - 260 + 1)*TPAD;
    else row = (b - 388 + 1)*TPAD + 129;
    uint32_t* T32 = reinterpret_cast<uint32_t*>(g_X);
#pragma unroll
    for (int s = 0; s < 2; s++)
        T32[((size_t)s*TROWS + row)*512 + cu] = 0u;
}

// ---------------- input transpose + split ----------------
__global__ void xsplit_kernel(const float* __restrict__ in) {
    __shared__ float t[32][33];
    int px0 = blockIdx.x << 5;
    int cc0 = blockIdx.y << 5;
    int tid = threadIdx.x;
    int tx = tid & 31, ty = tid >> 5;
#pragma unroll
    for (int i = 0; i < 4; i++) {
        int c = cc0 + ty + i*8;
        t[ty + i*8][tx] = in[(size_t)c*HW + px0 + tx];
    }
    __syncthreads();
    uint32_t* X32 = reinterpret_cast<uint32_t*>(g_X);
    const size_t SPLIT32 = (size_t)TROWS*CIN/2;
#pragma unroll
    for (int pass = 0; pass < 2; pass++) {
        int px_l = (tid >> 4) + (pass << 4);
        int cp2 = tid & 15;
        float v0 = t[cp2*2][px_l], v1 = t[cp2*2+1][px_l];
        __half h0, m0, h1, m1;
        split2(v0, h0, m0);
        split2(v1, h1, m1);
        int pix = px0 + px_l;
        int row = (pix >> 7) + 1;
        int col = (pix & 127) + 1;
        size_t o32 = (((size_t)(row*TPAD + col))*CIN + cc0)/2 + cp2;
        X32[o32] = pk(h0, h1);
        X32[SPLIT32 + o32] = pk(m0, m1);
    }
}

// ---------------- conv3x3: 128px x 32co tiles, fp16 split GEMM, A shared across kx ----------------
__global__ __launch_bounds__(256, 3)
void conv3_mma_kernel(const float* __restrict__ bc) {
    extern __shared__ char smem[];
    const uint32_t sb0 = smem_u32(smem);
    __shared__ unsigned s_tile;
    __shared__ float bsm[32];

    const int tid = threadIdx.x;
    const int lane = tid & 31;
    const int wid = tid >> 5;
    const int wm = wid >> 1;          // 0..3 (pixel dim, 32 px each)
    const int wn = wid & 1;           // 0..1 (co dim, 16 co each)

    const uint32_t Aoff = (uint32_t)(((lane & 7) + ((lane >> 3) & 1)*8)*80 + (lane >> 4)*16);
    const uint32_t Boff = (uint32_t)(((lane & 7) + (lane >> 4)*8)*80 + ((lane >> 3) & 1)*16);

    const char* Xg = (const char*)g_X;
    const char* Wg = (const char*)g_Ws;

    while (true) {
        if (tid == 0) s_tile = atomicAdd(&g_tile, 1u);
        __syncthreads();
        unsigned t = s_tile;
        __syncthreads();
        if (t >= NTILES) break;
        const int y = (int)(t >> 4);
        const int tn = (int)(t & 15);
        const int con0 = tn << 5;

        if (tid < 32) bsm[tid] = bc[con0 + tid];

        float acc_hi[2][2][4];
        float acc_lo[2][2][4];
#pragma unroll
        for (int a = 0; a < 2; a++)
#pragma unroll
            for (int b = 0; b < 2; b++)
#pragma unroll
                for (int c = 0; c < 4; c++) { acc_hi[a][b][c] = 0.f; acc_lo[a][b][c] = 0.f; }

        auto load_stage = [&](int s) {
            int ky = s >> 5, chunk = s & 31;
            int c0b = chunk << 6;
            int r0 = (y + ky)*TPAD;
            uint32_t buf = sb0 + (uint32_t)(s & 1)*STAGE_SZ;
            for (int i = tid; i < 1040; i += 256) {
                int sa = (i >= 520) ? 1 : 0;
                int j = i - sa*520;
                int row = j >> 2, q = j & 3;
                const char* src = Xg + (((size_t)sa*TROWS + r0 + row) << 11) + c0b + (q << 4);
                cp16(buf + sa*10400 + row*80 + (q << 4), src);
            }
#pragma unroll
            for (int it = 0; it < 3; it++) {
                int i = tid + it*256;
                int kx = i >> 8;
                int j = i & 255;
                int sbp = j >> 7;
                int jj = j & 127;
                int row = jj >> 2, q = jj & 3;
                int tap = ky*3 + kx;
                const char* src = Wg + ((((size_t)sbp*9 + tap)*CMID + con0 + row) << 11) + c0b + (q << 4);
                cp16(buf + ABUF_SZ + kx*5120 + sbp*2560 + row*80 + (q << 4), src);
            }
            asm volatile("cp.async.commit_group;" ::: "memory");
        };

        load_stage(0);
        for (int s = 0; s < NSTAGES; s++) {
            if (s + 1 < NSTAGES) {
                load_stage(s + 1);
                asm volatile("cp.async.wait_group 1;" ::: "memory");
            } else {
                asm volatile("cp.async.wait_group 0;" ::: "memory");
            }
            __syncthreads();

            const uint32_t bufA = sb0 + (uint32_t)(s & 1)*STAGE_SZ;
            const uint32_t bufB = bufA + ABUF_SZ;

#pragma unroll
            for (int kx = 0; kx < 3; kx++) {
                const uint32_t aBase = bufA + (uint32_t)(kx + wm*32)*80 + Aoff;
                const uint32_t bBase = bufB + (uint32_t)kx*5120 + (uint32_t)(wn*16)*80 + Boff;
#pragma unroll
                for (int ks = 0; ks < 2; ks++) {
                    uint32_t bq0[4], bq1[4], aq[8];
                    ldsm4(bq0, bBase + ks*32);
                    ldsm4(bq1, bBase + 2560 + ks*32);
                    ldsm4(&aq[0], aBase + ks*32);
                    ldsm4(&aq[4], aBase + 16*80 + ks*32);
#pragma unroll
                    for (int mi = 0; mi < 2; mi++)
#pragma unroll
                        for (int ni = 0; ni < 2; ni++) {
                            mma16816(acc_hi[mi][ni], &aq[mi*4], &bq0[ni*2]);
                            mma16816(acc_lo[mi][ni], &aq[mi*4], &bq1[ni*2]);
                        }
                    ldsm4(&aq[0], aBase + 10400 + ks*32);
                    ldsm4(&aq[4], aBase + 10400 + 16*80 + ks*32);
#pragma unroll
                    for (int mi = 0; mi < 2; mi++)
#pragma unroll
                        for (int ni = 0; ni < 2; ni++)
                            mma16816(acc_lo[mi][ni], &aq[mi*4], &bq0[ni*2]);
                }
            }
            __syncthreads();
        }

        // ---- epilogue: relu(hi + lo/2048 + bias) -> g_conv1 ----
        const float INV2048 = 1.f/2048.f;
#pragma unroll
        for (int mi = 0; mi < 2; mi++)
#pragma unroll
            for (int ni = 0; ni < 2; ni++)
#pragma unroll
                for (int c = 0; c < 4; c++) {
                    int co = con0 + (wn << 4) + (ni << 3) + ((lane & 3) << 1) + (c & 1);
                    int px = (wm << 5) + (mi << 4) + (lane >> 2) + ((c >> 1) << 3);
                    float v = (acc_hi[mi][ni][c] + acc_lo[mi][ni][c]*INV2048) + bsm[co - con0];
                    g_conv1[(size_t)co*HW + (y << 7) + px] = fmaxf(v, 0.f);
                }
        __syncthreads();
    }
}

// ---------------- fused 1x1 convs + softmax + box decode (+ radix hist pass 1) ----------------
__global__ __launch_bounds__(256)
void conv1x1_decode_kernel(const float* __restrict__ Wcls, const float* __restrict__ bcls,
                           const float* __restrict__ Wbb,  const float* __restrict__ bbb,
                           const float* __restrict__ meta,
                           float* __restrict__ outP, float* __restrict__ outB) {
    extern __shared__ float dyn[];
    float* wsm = dyn;                       // [30][512]
    float* psm = dyn + 30*512;              // [4][64][30]
    float* osm = dyn + 30*512 + 4*64*30;    // [64][30]
    int tid = threadIdx.x;
    for (int i = tid; i < 30*512; i += 256) {
        int ch = i >> 9, c = i & 511;
        wsm[i] = (ch < 6) ? Wcls[ch*512 + c] : Wbb[(ch - 6)*512 + c];
    }
    __syncthreads();
    int q = tid >> 6, pxl = tid & 63;
    int px0 = blockIdx.x << 6;
    int px = px0 + pxl;
    float acc[30];
#pragma unroll
    for (int ch = 0; ch < 30; ch++) acc[ch] = 0.f;
    for (int cc = 0; cc < 128; cc++) {
        int c = (q << 7) + cc;
        float v = g_conv1[(size_t)c*HW + px];
#pragma unroll
        for (int ch = 0; ch < 30; ch++) acc[ch] += v * wsm[(ch << 9) + c];
    }
#pragma unroll
    for (int ch = 0; ch < 30; ch++) psm[(q*64 + pxl)*30 + ch] = acc[ch];
    __syncthreads();
    for (int i = tid; i < 64*30; i += 256) {
        int pl = i / 30, ch = i % 30;
        float s = psm[pl*30 + ch] + psm[(64 + pl)*30 + ch]
                + psm[(128 + pl)*30 + ch] + psm[(192 + pl)*30 + ch];
        float v;
        if (ch < 6) v = s + bcls[ch];
        else { v = s + bbb[ch - 6]; outB[(ch - 6)*HW + px0 + pl] = v; }
        osm[pl*30 + ch] = v;
    }
    __syncthreads();
    float im_h = meta[0], im_w = meta[1];
    for (int i = tid; i < 64*6; i += 256) {
        int pl = i / 6, a = i % 6;
        int pix = px0 + pl;
        float ss = osm[pl*30 + a];
        int ao = (a < 3) ? a + 3 : a - 3;
        float so = osm[pl*30 + ao];
        float m = fmaxf(ss, so);
        float e1 = expf(ss - m), e2 = expf(so - m);
        float p = e1 / (e1 + e2);
        outP[a*HW + pix] = p;
        g_scores[pix*6 + a] = p;
        atomicAdd(&g_hist[__float_as_uint(p) >> 20], 1u);

        float dims = c_dims[a];
        int x = pix & 127, yv = pix >> 7;
        float cxa = ((float)x + 0.5f) * 16.f;
        float cya = ((float)yv + 0.5f) * 16.f;
        float d0 = osm[pl*30 + 6 + a*4 + 0];
        float d1 = osm[pl*30 + 6 + a*4 + 1];
        float d2 = osm[pl*30 + 6 + a*4 + 2];
        float d3 = osm[pl*30 + 6 + a*4 + 3];
        float pcx = d0*dims + cxa;
        float pcy = d1*dims + cya;
        float pw  = expf(d2)*dims;
        float ph  = expf(d3)*dims;
        float bx1 = fminf(fmaxf(pcx - 0.5f*pw, 0.f), im_w);
        float by1 = fminf(fmaxf(pcy - 0.5f*ph, 0.f), im_h);
        float bx2 = fminf(fmaxf(pcx + 0.5f*pw, 0.f), im_w);
        float by2 = fminf(fmaxf(pcy + 0.5f*ph, 0.f), im_h);
        *reinterpret_cast<float4*>(&g_boxes[(pix*6 + a)*4]) = make_float4(bx1, by1, bx2, by2);
    }
}

// ---------------- radix select (2 passes; sortsel resolves the rest exactly) ----------------
__global__ void hist_kernel() {
    int i = blockIdx.x*blockDim.x + threadIdx.x;
    if (i >= NANCH) return;
    unsigned bits = __float_as_uint(g_scores[i]);
    if ((bits >> 20) == g_state[0]) atomicAdd(&g_hist[(bits >> 8) & 0xFFFu], 1u);
}

__global__ void sel_kernel(int pass) {
    __shared__ unsigned sa[4096], sbv[4096];
    int tid = threadIdx.x;
    for (int i = tid; i < 4096; i += 1024) {
        sa[i] = g_hist[i];
        g_hist[i] = 0u;
    }
    __syncthreads();
    unsigned *src = sa, *dst = sbv;
    for (int off = 1; off < 4096; off <<= 1) {
        for (int i = tid; i < 4096; i += 1024)
            dst[i] = src[i] + ((i + off < 4096) ? src[i + off] : 0u);
        __syncthreads();
        unsigned* tp = src; src = dst; dst = tp;
    }
    unsigned need = (pass == 1) ? (unsigned)PRE_N : g_state[1];
    for (int i = tid; i < 4096; i += 1024) {
        unsigned cg = (i + 1 < 4096) ? src[i + 1] : 0u;
        unsigned ci = src[i];
        if (ci >= need && cg < need) {
            if (pass == 1) { g_state[0] = (unsigned)i; g_state[1] = need - cg; }
            else           { g_state[4] = (g_state[0] << 12) | (unsigned)i; }  // 24-bit prefix
        }
    }
}

__global__ void compact_kernel() {
    int i = blockIdx.x*blockDim.x + threadIdx.x;
    if (i >= NANCH) return;
    unsigned pre = __float_as_uint(g_scores[i]) >> 8;
    unsigned thr = g_state[4];
    if (pre > thr) {
        unsigned p = atomicAdd(&g_cnt[0], 1u);
        if (p < PRE_N + 256) g_great[p] = i;
    } else if (pre == thr) {
        unsigned p = atomicAdd(&g_cnt[1], 1u);
        if (p < 4096) g_tie[p] = i;
    }
}

// ---------------- sort-based finalize ----------------
__global__ void sortsel_kernel() {
    extern __shared__ unsigned long long keys[];   // 8192
    int tid = threadIdx.x;
    unsigned nG = min(g_cnt[0], (unsigned)PRE_N);
    unsigned nT = min(min(g_cnt[1], 4096u), 8192u - nG);
    unsigned total = nG + nT;
    for (int i = tid; i < 8192; i += 1024) {
        unsigned long long k = 0xFFFFFFFFFFFFFFFFull;
        if (i < (int)total) {
            int idx = (i < (int)nG) ? g_great[i] : g_tie[i - nG];
            unsigned bits = __float_as_uint(g_scores[idx]);
            k = ((unsigned long long)(~bits) << 32) | (unsigned)idx;
        }
        keys[i] = k;
    }
    __syncthreads();
    for (int k2 = 2; k2 <= 8192; k2 <<= 1) {
        for (int j = k2 >> 1; j > 0; j >>= 1) {
            for (int i = tid; i < 8192; i += 1024) {
                int ixj = i ^ j;
                if (ixj > i) {
                    bool up = ((i & k2) == 0);
                    unsigned long long a = keys[i], b = keys[ixj];
                    if ((a > b) == up) { keys[i] = b; keys[ixj] = a; }
                }
            }
            __syncthreads();
        }
    }
    for (int s2 = tid; s2 < PRE_N; s2 += 1024) {
        int idx = (int)(keys[s2] & 0xFFFFFFFFull);
        g_sel[s2] = idx;
        float4 bx = *reinterpret_cast<const float4*>(&g_boxes[idx*4]);
        *reinterpret_cast<float4*>(&g_selbox[s2*4]) = bx;
        g_selscore[s2] = g_scores[idx];
    }
}

// ---------------- greedy NMS (cached per-warp maxima, 2 barriers/iter) ----------------
__global__ void nms_kernel(float* __restrict__ rois) {
    extern __shared__ float sm[];
    float* X1 = sm;
    float* Y1 = sm + PRE_N;
    float* X2 = sm + 2*PRE_N;
    float* Y2 = sm + 3*PRE_N;
    float* AR = sm + 4*PRE_N;
    int*   KEEP = (int*)(sm + 5*PRE_N);
    __shared__ unsigned long long wmax[32];
    __shared__ float bb[6];

    int tid = threadIdx.x;
    int lane = tid & 31, wid = tid >> 5;
    float ms[6];
#pragma unroll
    for (int k = 0; k < 6; k++) {
        int i = tid + (k << 10);
        ms[k] = (i < PRE_N) ? g_selscore[i] : -1.f;
    }
    for (int i = tid; i < PRE_N; i += 1024) {
        float x1 = g_selbox[i*4+0], y1 = g_selbox[i*4+1];
        float x2 = g_selbox[i*4+2], y2 = g_selbox[i*4+3];
        X1[i] = x1; Y1[i] = y1; X2[i] = x2; Y2[i] = y2;
        AR[i] = fmaxf(x2 - x1, 0.f) * fmaxf(y2 - y1, 0.f);
    }
    bool dirty = true;
    __syncthreads();

    for (int it = 0; it < POST_N; it++) {
        if (dirty) {
            unsigned long long best = 0ull;
#pragma unroll
            for (int k = 0; k < 6; k++) {
                float v = ms[k];
                if (v >= 0.f) {
                    int i = tid + (k << 10);
                    unsigned long long kk = ((unsigned long long)__float_as_uint(v) << 32)
                                          | (unsigned)(0xFFFFFFFFu - (unsigned)i);
                    if (kk > best) best = kk;
                }
            }
#pragma unroll
            for (int off = 16; off > 0; off >>= 1) {
                unsigned long long o = __shfl_down_sync(0xffffffffu, best, off);
                if (o > best) best = o;
            }
            if (lane == 0) wmax[wid] = best;
        }
        __syncthreads();
        if (wid == 0) {
            unsigned long long b = wmax[lane];
#pragma unroll
            for (int off = 16; off > 0; off >>= 1) {
                unsigned long long o = __shfl_down_sync(0xffffffffu, b, off);
                if (o > b) b = o;
            }
            if (lane == 0) {
                bool valid = (b != 0ull);
                int j = valid ? (int)(0xFFFFFFFFu - (unsigned)(b & 0xFFFFFFFFull)) : 0;
                KEEP[it] = valid ? j : -1;
                bb[0] = X1[j]; bb[1] = Y1[j]; bb[2] = X2[j]; bb[3] = Y2[j];
                bb[4] = AR[j]; bb[5] = valid ? 1.f : 0.f;
            }
        }
        __syncthreads();
        bool changed = false;
        if (bb[5] > 0.f) {
            float bx1 = bb[0], by1 = bb[1], bx2 = bb[2], by2 = bb[3], ba = bb[4];
#pragma unroll
            for (int k = 0; k < 6; k++) {
                if (ms[k] >= 0.f) {
                    int i = tid + (k << 10);
                    float iw = fmaxf(fminf(X2[i], bx2) - fmaxf(X1[i], bx1), 0.f);
                    float ih = fmaxf(fminf(Y2[i], by2) - fmaxf(Y1[i], by1), 0.f);
                    float inter = iw * ih;
                    float iou = inter / (AR[i] + ba - inter + 1e-9f);
                    if (iou > 0.7f) { ms[k] = -1.f; changed = true; }
                }
            }
        }
        dirty = (__ballot_sync(0xffffffffu, changed) != 0u);
    }

    __syncthreads();
    if (tid < POST_N) {
        int j = KEEP[tid];
        float* o = rois + tid*5;
        if (j >= 0) { o[0] = 0.f; o[1] = X1[j]; o[2] = Y1[j]; o[3] = X2[j]; o[4] = Y2[j]; }
        else        { o[0] = 0.f; o[1] = 0.f;  o[2] = 0.f;  o[3] = 0.f;  o[4] = 0.f; }
    }
}

// ---------------- launch ----------------
extern "C" void kernel_launch(void* const* d_in, const int* in_sizes, int n_in,
                              void* d_out, int out_size) {
    const float* base = (const float*)d_in[0];
    const float* meta = (const float*)d_in[1];
    const float* Wc   = (const float*)d_in[3];
    const float* bc   = (const float*)d_in[4];
    const float* Wcls = (const float*)d_in[5];
    const float* bcls = (const float*)d_in[6];
    const float* Wbb  = (const float*)d_in[7];
    const float* bbb  = (const float*)d_in[8];

    float* out  = (float*)d_out;
    float* outP = out + POST_N*5;
    float* outB = outP + NA*HW;

    const int C1X1_SMEM = (30*512 + 4*64*30 + 64*30) * 4;   // 99840
    cudaFuncSetAttribute(conv3_mma_kernel,      cudaFuncAttributeMaxDynamicSharedMemorySize, SMEM_SZ);
    cudaFuncSetAttribute(conv1x1_decode_kernel, cudaFuncAttributeMaxDynamicSharedMemorySize, C1X1_SMEM);
    cudaFuncSetAttribute(sortsel_kernel,        cudaFuncAttributeMaxDynamicSharedMemorySize, 65536);
    cudaFuncSetAttribute(nms_kernel,            cudaFuncAttributeMaxDynamicSharedMemorySize, 140000);

    wsplit_kernel<<<(CMID*CIN + 255)/256, 256>>>(Wc);
    tborder_kernel<<<(516*512 + 255)/256, 256>>>();
    xsplit_kernel<<<dim3(HW/32, CIN/32), 256>>>(base);
    conv3_mma_kernel<<<456, 256, SMEM_SZ>>>(bc);
    conv1x1_decode_kernel<<<256, 256, C1X1_SMEM>>>(Wcls, bcls, Wbb, bbb, meta, outP, outB);
    sel_kernel<<<1, 1024>>>(1);
    hist_kernel<<<NANCH/256, 256>>>();
    sel_kernel<<<1, 1024>>>(2);
    compact_kernel<<<NANCH/256, 256>>>();
    sortsel_kernel<<<1, 1024, 65536>>>();
    nms_kernel<<<1, 1024, (5*PRE_N + 512) * 4>>>(out);
}